// round 1
// baseline (speedup 1.0000x reference)
#include <cuda_runtime.h>
#include <math.h>

#define D_MODEL 1024
#define NHEADS  16
#define HD      64
#define BATCH   4
#define SEQ     2048
#define MAXSEQ  2048
#define BH      (BATCH*NHEADS)     // 64
#define MTOK    (BATCH*SEQ)        // 8192

// ---------------- scratch (device globals: allocation-free) ----------------
__device__ float g_q[(size_t)BH*SEQ*HD];
__device__ float g_k[(size_t)BH*SEQ*HD];
__device__ float g_v[(size_t)BH*SEQ*HD];
__device__ float g_ctx[(size_t)MTOK*D_MODEL];

// ---------------- SGEMM: C[M,N] = A[M,K] @ B[N,K]^T ----------------
// MODE 0: A = g_ctx, C = Cout (fp32) with +bias[n]     (output projection)
// MODE 1: A = param, C scatter into [b,h,s,d] q/k/v scratch (SEL picks target)
#define BM 128
#define BN 128
#define BKG 16

template<int MODE, int SEL>
__global__ __launch_bounds__(256)
void sgemm_kernel(const float* __restrict__ A, const float* __restrict__ B,
                  const float* __restrict__ bias, float* __restrict__ Cout,
                  int M, int N, int K)
{
    __shared__ float As[BKG][BM + 4];   // [k][m], row stride 132 (16B-aligned rows)
    __shared__ float Bs[BKG][BN + 4];   // [k][n]

    const int tid = threadIdx.x;
    const int tx  = tid & 15;
    const int ty  = tid >> 4;
    const int m0  = blockIdx.x * BM;
    const int n0  = blockIdx.y * BN;

    const float* Ap = (MODE == 0) ? (const float*)g_ctx : A;

    float acc[8][8];
#pragma unroll
    for (int i = 0; i < 8; i++)
#pragma unroll
        for (int j = 0; j < 8; j++) acc[i][j] = 0.0f;

    for (int kt = 0; kt < K; kt += BKG) {
        // Load A,B tiles (128x16) transposed into shared. 512 float4 vectors, 2/thread.
#pragma unroll
        for (int r = 0; r < 2; r++) {
            int vi  = tid + r * 256;        // 0..511
            int row = vi >> 2;              // 0..127
            int kc4 = (vi & 3) * 4;         // 0,4,8,12
            float4 av = *(const float4*)(Ap + (size_t)(m0 + row) * K + kt + kc4);
            As[kc4 + 0][row] = av.x; As[kc4 + 1][row] = av.y;
            As[kc4 + 2][row] = av.z; As[kc4 + 3][row] = av.w;
            float4 bv = *(const float4*)(B + (size_t)(n0 + row) * K + kt + kc4);
            Bs[kc4 + 0][row] = bv.x; Bs[kc4 + 1][row] = bv.y;
            Bs[kc4 + 2][row] = bv.z; Bs[kc4 + 3][row] = bv.w;
        }
        __syncthreads();

#pragma unroll
        for (int kk = 0; kk < BKG; kk++) {
            float4 a0 = *(const float4*)&As[kk][ty * 8];
            float4 a1 = *(const float4*)&As[kk][ty * 8 + 4];
            float4 b0 = *(const float4*)&Bs[kk][tx * 8];
            float4 b1 = *(const float4*)&Bs[kk][tx * 8 + 4];
            float a[8] = {a0.x, a0.y, a0.z, a0.w, a1.x, a1.y, a1.z, a1.w};
            float b[8] = {b0.x, b0.y, b0.z, b0.w, b1.x, b1.y, b1.z, b1.w};
#pragma unroll
            for (int i = 0; i < 8; i++)
#pragma unroll
                for (int j = 0; j < 8; j++) acc[i][j] += a[i] * b[j];
        }
        __syncthreads();
    }

    // Epilogue
#pragma unroll
    for (int i = 0; i < 8; i++) {
        int m = m0 + ty * 8 + i;
#pragma unroll
        for (int j = 0; j < 8; j++) {
            int n = n0 + tx * 8 + j;
            if (MODE == 0) {
                Cout[(size_t)m * N + n] = acc[i][j] + bias[n];
            } else {
                int bb = m >> 11;           // m / SEQ
                int s  = m & (SEQ - 1);
                int h  = n >> 6;            // n / HD
                int d  = n & (HD - 1);
                float* C = (SEL == 0) ? g_q : (SEL == 1) ? g_k : g_v;
                C[(((size_t)(bb * NHEADS + h) * SEQ) + s) * HD + d] = acc[i][j];
            }
        }
    }
}

// ---------------- Flash attention (fp32) with relative bias ----------------
// grid: (SEQ/BQ, BH), block 256. Per thread: S tile 4x2, O tile 4x4.
#define BQ  64
#define BKK 32

__global__ __launch_bounds__(256)
void attn_kernel(const float* __restrict__ bias_table)
{
    __shared__ float Qs[HD][BQ + 4];      // [d][q]  stride 68 -> 16B aligned rows
    __shared__ float Ks[HD][BKK + 1];     // [d][k]  stride 33 (scalar reads)
    __shared__ float Vs[BKK][HD + 4];     // [k][d]  stride 68
    __shared__ float Ps[BQ][BKK + 1];     // [q][k]  stride 33 (scalar reads)
    __shared__ float sbias[BQ + BKK];     // 95 used

    const int tid = threadIdx.x;
    const int tx  = tid & 15;
    const int ty  = tid >> 4;
    const int bh  = blockIdx.y;
    const int b   = bh >> 4;
    const int h   = bh & 15;
    const int q0  = blockIdx.x * BQ;

    const float* Qg = g_q + ((size_t)bh * SEQ + q0) * HD;
    const float* Kg = g_k + (size_t)bh * SEQ * HD;
    const float* Vg = g_v + (size_t)bh * SEQ * HD;

    // Load Q tile transposed (64x64): 1024 float4, 4/thread
#pragma unroll
    for (int r = 0; r < 4; r++) {
        int vi  = tid + r * 256;     // 0..1023
        int row = vi >> 4;           // q row 0..63
        int c4  = (vi & 15) * 4;     // d offset
        float4 v = *(const float4*)(Qg + (size_t)row * HD + c4);
        Qs[c4 + 0][row] = v.x; Qs[c4 + 1][row] = v.y;
        Qs[c4 + 2][row] = v.z; Qs[c4 + 3][row] = v.w;
    }

    float Oacc[4][4];
    float mrow[4], lrow[4];
#pragma unroll
    for (int i = 0; i < 4; i++) {
        mrow[i] = -3.0e38f; lrow[i] = 0.0f;
#pragma unroll
        for (int j = 0; j < 4; j++) Oacc[i][j] = 0.0f;
    }

    const float scale = 0.125f;   // hd^-0.5

    for (int k0 = 0; k0 < SEQ; k0 += BKK) {
        // Load K (transposed) and V tiles: 512 float4 each, 2/thread
#pragma unroll
        for (int r = 0; r < 2; r++) {
            int vi  = tid + r * 256;   // 0..511
            int row = vi >> 4;         // k row 0..31
            int c4  = (vi & 15) * 4;
            float4 kv = *(const float4*)(Kg + (size_t)(k0 + row) * HD + c4);
            Ks[c4 + 0][row] = kv.x; Ks[c4 + 1][row] = kv.y;
            Ks[c4 + 2][row] = kv.z; Ks[c4 + 3][row] = kv.w;
            float4 vv = *(const float4*)(Vg + (size_t)(k0 + row) * HD + c4);
            *(float4*)&Vs[row][c4] = vv;
        }
        // Relative-bias window: diff = (q-q0)-(k-k0) in [-31,63] -> 95 values
        if (tid < BQ + BKK - 1) {
            int rel = q0 - k0 + tid - (BKK - 1) + (MAXSEQ - 1);
            rel = min(max(rel, 0), 2 * MAXSEQ - 2);
            sbias[tid] = bias_table[rel * NHEADS + h];
        }
        __syncthreads();

        // S = Q @ K^T  (per-thread 4 rows x 2 cols)
        float s[4][2] = {{0, 0}, {0, 0}, {0, 0}, {0, 0}};
#pragma unroll
        for (int kk = 0; kk < HD; kk++) {
            float4 a = *(const float4*)&Qs[kk][ty * 4];
            float b0 = Ks[kk][tx * 2], b1 = Ks[kk][tx * 2 + 1];
            s[0][0] += a.x * b0; s[0][1] += a.x * b1;
            s[1][0] += a.y * b0; s[1][1] += a.y * b1;
            s[2][0] += a.z * b0; s[2][1] += a.z * b1;
            s[3][0] += a.w * b0; s[3][1] += a.w * b1;
        }

        // scale + bias, row max
        float rmax[4];
#pragma unroll
        for (int i = 0; i < 4; i++) {
#pragma unroll
            for (int j = 0; j < 2; j++) {
                int diff = (ty * 4 + i) - (tx * 2 + j) + (BKK - 1);
                s[i][j] = s[i][j] * scale + sbias[diff];
            }
            rmax[i] = fmaxf(s[i][0], s[i][1]);
        }
#pragma unroll
        for (int off = 1; off < 16; off <<= 1)
#pragma unroll
            for (int i = 0; i < 4; i++)
                rmax[i] = fmaxf(rmax[i], __shfl_xor_sync(0xffffffffu, rmax[i], off));

        // online softmax update
        float rsum[4];
#pragma unroll
        for (int i = 0; i < 4; i++) {
            float mnew  = fmaxf(mrow[i], rmax[i]);
            float alpha = __expf(mrow[i] - mnew);
            mrow[i] = mnew;
            float p0 = __expf(s[i][0] - mnew);
            float p1 = __expf(s[i][1] - mnew);
            s[i][0] = p0; s[i][1] = p1;
            rsum[i] = p0 + p1;
            lrow[i] *= alpha;
#pragma unroll
            for (int j = 0; j < 4; j++) Oacc[i][j] *= alpha;
        }
#pragma unroll
        for (int off = 1; off < 16; off <<= 1)
#pragma unroll
            for (int i = 0; i < 4; i++)
                rsum[i] += __shfl_xor_sync(0xffffffffu, rsum[i], off);
#pragma unroll
        for (int i = 0; i < 4; i++) lrow[i] += rsum[i];

        // stage P to shared
#pragma unroll
        for (int i = 0; i < 4; i++) {
            Ps[ty * 4 + i][tx * 2 + 0] = s[i][0];
            Ps[ty * 4 + i][tx * 2 + 1] = s[i][1];
        }
        __syncthreads();

        // O += P @ V  (per-thread 4 rows x 4 d-cols)
#pragma unroll
        for (int kk = 0; kk < BKK; kk++) {
            float4 bv = *(const float4*)&Vs[kk][tx * 4];
            float a0 = Ps[ty * 4 + 0][kk];
            float a1 = Ps[ty * 4 + 1][kk];
            float a2 = Ps[ty * 4 + 2][kk];
            float a3 = Ps[ty * 4 + 3][kk];
            Oacc[0][0] += a0 * bv.x; Oacc[0][1] += a0 * bv.y; Oacc[0][2] += a0 * bv.z; Oacc[0][3] += a0 * bv.w;
            Oacc[1][0] += a1 * bv.x; Oacc[1][1] += a1 * bv.y; Oacc[1][2] += a1 * bv.z; Oacc[1][3] += a1 * bv.w;
            Oacc[2][0] += a2 * bv.x; Oacc[2][1] += a2 * bv.y; Oacc[2][2] += a2 * bv.z; Oacc[2][3] += a2 * bv.w;
            Oacc[3][0] += a3 * bv.x; Oacc[3][1] += a3 * bv.y; Oacc[3][2] += a3 * bv.z; Oacc[3][3] += a3 * bv.w;
        }
        __syncthreads();
    }

    // epilogue: ctx[b, s, h*HD + d]  (fp32)
#pragma unroll
    for (int i = 0; i < 4; i++) {
        float inv = 1.0f / lrow[i];
        int token = b * SEQ + q0 + ty * 4 + i;
        float4 o = make_float4(Oacc[i][0] * inv, Oacc[i][1] * inv,
                               Oacc[i][2] * inv, Oacc[i][3] * inv);
        *(float4*)&g_ctx[(size_t)token * D_MODEL + h * HD + tx * 4] = o;
    }
}

// ---------------- launch ----------------
extern "C" void kernel_launch(void* const* d_in, const int* in_sizes, int n_in,
                              void* d_out, int out_size)
{
    const float* x  = (const float*)d_in[0];
    const float* Wq = (const float*)d_in[1];
    const float* Wk = (const float*)d_in[2];
    const float* Wv = (const float*)d_in[3];
    const float* Wo = (const float*)d_in[4];
    const float* bo = (const float*)d_in[5];
    const float* bt = (const float*)d_in[6];
    float* out = (float*)d_out;

    dim3 gg(MTOK / BM, D_MODEL / BN);   // (64, 8)

    sgemm_kernel<1, 0><<<gg, 256>>>(x, Wq, nullptr, nullptr, MTOK, D_MODEL, D_MODEL);
    sgemm_kernel<1, 1><<<gg, 256>>>(x, Wk, nullptr, nullptr, MTOK, D_MODEL, D_MODEL);
    sgemm_kernel<1, 2><<<gg, 256>>>(x, Wv, nullptr, nullptr, MTOK, D_MODEL, D_MODEL);

    attn_kernel<<<dim3(SEQ / BQ, BH), 256>>>(bt);

    sgemm_kernel<0, 0><<<gg, 256>>>(nullptr, Wo, bo, out, MTOK, D_MODEL, D_MODEL);
}

// round 4
// speedup vs baseline: 2.5345x; 2.5345x over previous
#include <cuda_runtime.h>
#include <cuda_bf16.h>
#include <stdint.h>

#define D_MODEL 1024
#define NHEADS  16
#define HD      64
#define BATCH   4
#define SEQ     2048
#define BH      64
#define MTOK    8192
#define QSCALE  0.18033688011112042f   // 0.125 * log2(e)
#define LOG2E   1.4426950408889634f

// ---------------- scratch globals (allocation-free) ----------------
__device__ __nv_bfloat16 g_qh[8388608], g_ql[8388608];
__device__ __nv_bfloat16 g_kh[8388608], g_kl[8388608];
__device__ __nv_bfloat16 g_vh[8388608], g_vl[8388608];
__device__ __nv_bfloat16 g_xh[8388608], g_xl[8388608];
__device__ __nv_bfloat16 g_wh[4194304], g_wl[4194304];
__device__ __nv_bfloat16 g_ch[8388608], g_cl[8388608];

// ---------------- helpers ----------------
__device__ __forceinline__ uint32_t su32(const void* p) {
    uint32_t a;
    asm("{ .reg .u64 t; cvta.to.shared.u64 t, %1; cvt.u32.u64 %0, t; }" : "=r"(a) : "l"(p));
    return a;
}
__device__ __forceinline__ void cpa16(uint32_t dst, const void* src) {
    asm volatile("cp.async.cg.shared.global [%0], [%1], 16;" :: "r"(dst), "l"(src));
}
#define CP_COMMIT() asm volatile("cp.async.commit_group;" ::: "memory")
#define CP_WAIT0()  asm volatile("cp.async.wait_group 0;" ::: "memory")
#define CP_WAIT1()  asm volatile("cp.async.wait_group 1;" ::: "memory")

__device__ __forceinline__ void ldsm4(uint32_t* r, uint32_t addr) {
    asm volatile("ldmatrix.sync.aligned.m8n8.x4.shared.b16 {%0,%1,%2,%3}, [%4];"
                 : "=r"(r[0]), "=r"(r[1]), "=r"(r[2]), "=r"(r[3]) : "r"(addr));
}
__device__ __forceinline__ void ldsm4t(uint32_t* r, uint32_t addr) {
    asm volatile("ldmatrix.sync.aligned.m8n8.x4.trans.shared.b16 {%0,%1,%2,%3}, [%4];"
                 : "=r"(r[0]), "=r"(r[1]), "=r"(r[2]), "=r"(r[3]) : "r"(addr));
}
__device__ __forceinline__ void mma_bf16(float* c, const uint32_t* a, const uint32_t* b) {
    asm volatile("mma.sync.aligned.m16n8k16.row.col.f32.bf16.bf16.f32 "
                 "{%0,%1,%2,%3}, {%4,%5,%6,%7}, {%8,%9}, {%0,%1,%2,%3};"
                 : "+f"(c[0]), "+f"(c[1]), "+f"(c[2]), "+f"(c[3])
                 : "r"(a[0]), "r"(a[1]), "r"(a[2]), "r"(a[3]), "r"(b[0]), "r"(b[1]));
}
__device__ __forceinline__ float ex2f(float x) {
    float r; asm("ex2.approx.f32 %0, %1;" : "=f"(r) : "f"(x)); return r;
}
// split pair (v0,v1) -> packed bf16 hi pair + bf16 lo-residual pair
__device__ __forceinline__ void split2(float v0, float v1, uint32_t& hi, uint32_t& lo) {
    uint32_t b0 = __float_as_uint(v0), b1 = __float_as_uint(v1);
    uint32_t h0 = (b0 + 0x7FFFu + ((b0 >> 16) & 1u)) & 0xFFFF0000u;
    uint32_t h1 = (b1 + 0x7FFFu + ((b1 >> 16) & 1u)) & 0xFFFF0000u;
    hi = (h0 >> 16) | h1;
    float l0 = v0 - __uint_as_float(h0);
    float l1 = v1 - __uint_as_float(h1);
    asm("cvt.rn.bf16x2.f32 %0, %1, %2;" : "=r"(lo) : "f"(l1), "f"(l0));
}

// ---------------- prep: fp32 -> bf16 hi/lo ----------------
__global__ void split_x_kernel(const float* __restrict__ src) {
    for (size_t i = (size_t)blockIdx.x * blockDim.x + threadIdx.x; i < (size_t)MTOK * D_MODEL;
         i += (size_t)gridDim.x * blockDim.x) {
        float v = src[i];
        __nv_bfloat16 h = __float2bfloat16(v);
        g_xh[i] = h;
        g_xl[i] = __float2bfloat16(v - __bfloat162float(h));
    }
}
__global__ void split_w_kernel(const float* __restrict__ src, int idx) {
    size_t off = (size_t)idx * 1048576;
    for (size_t i = (size_t)blockIdx.x * blockDim.x + threadIdx.x; i < 1048576;
         i += (size_t)gridDim.x * blockDim.x) {
        float v = src[i];
        __nv_bfloat16 h = __float2bfloat16(v);
        g_wh[off + i] = h;
        g_wl[off + i] = __float2bfloat16(v - __bfloat162float(h));
    }
}

// ---------------- projection GEMM: C[8192,1024] = A @ W^T, split bf16, mma.sync ----
// MODE 0:Q(scaled) 1:K 2:V 3:O(fp32 out + bias)
// stage: 4 tiles x [128 rows x 32 k-elems], row stride 80B (64B data + 16B pad)
#define PST 40960

template<int MODE>
__global__ void __launch_bounds__(256, 1)
proj_kernel(const float* __restrict__ bias, float* __restrict__ out)
{
    extern __shared__ char smem[];
    const uint32_t sb = su32(smem);
    const int tid = threadIdx.x;
    const int lane = tid & 31, wid = tid >> 5;
    const int wm = wid >> 2, wn = wid & 3;
    const int g = lane >> 2, tig = lane & 3;
    const int m0 = blockIdx.x * 128, n0 = blockIdx.y * 128;

    const __nv_bfloat16* Ah = (MODE == 3) ? g_ch : g_xh;
    const __nv_bfloat16* Al = (MODE == 3) ? g_cl : g_xl;
    const __nv_bfloat16* Bh = g_wh + (size_t)MODE * 1048576;
    const __nv_bfloat16* Bl = g_wl + (size_t)MODE * 1048576;

    float acc[4][4][4];
#pragma unroll
    for (int i = 0; i < 4; i++)
#pragma unroll
        for (int j = 0; j < 4; j++)
#pragma unroll
            for (int e = 0; e < 4; e++) acc[i][j][e] = 0.0f;

    auto load_stage = [&](int kt, int buf) {
        uint32_t base = sb + buf * PST;
#pragma unroll
        for (int t = 0; t < 8; t++) {
            int vi = tid + t * 256;
            int tile = vi >> 9;
            int row = (vi >> 2) & 127;
            int ch = vi & 3;
            const __nv_bfloat16* src;
            if      (tile == 0) src = Ah + (size_t)(m0 + row) * 1024 + kt + ch * 8;
            else if (tile == 1) src = Al + (size_t)(m0 + row) * 1024 + kt + ch * 8;
            else if (tile == 2) src = Bh + (size_t)(n0 + row) * 1024 + kt + ch * 8;
            else                src = Bl + (size_t)(n0 + row) * 1024 + kt + ch * 8;
            cpa16(base + tile * 10240 + row * 80 + ch * 16, src);
        }
        CP_COMMIT();
    };

    load_stage(0, 0);
    for (int s = 0; s < 32; s++) {
        if (s < 31) { load_stage((s + 1) * 32, (s + 1) & 1); CP_WAIT1(); }
        else CP_WAIT0();
        __syncthreads();
        uint32_t base = sb + (s & 1) * PST;
#pragma unroll
        for (int ks = 0; ks < 2; ks++) {
            uint32_t afh[4][4], afl[4][4], bfh[2][4], bfl[2][4];
#pragma unroll
            for (int mf = 0; mf < 4; mf++) {
                uint32_t a = base + (uint32_t)(wm * 64 + mf * 16 + (lane & 15)) * 80
                           + (ks * 16 + (lane >> 4) * 8) * 2;
                ldsm4(afh[mf], a);
                ldsm4(afl[mf], a + 10240);
            }
#pragma unroll
            for (int g2 = 0; g2 < 2; g2++) {
                uint32_t a = base + 20480
                           + (uint32_t)(wn * 32 + g2 * 16 + (lane & 7) + ((lane >> 4) << 3)) * 80
                           + (ks * 16 + ((lane >> 3) & 1) * 8) * 2;
                ldsm4(bfh[g2], a);
                ldsm4(bfl[g2], a + 10240);
            }
#pragma unroll
            for (int mf = 0; mf < 4; mf++)
#pragma unroll
                for (int nf = 0; nf < 4; nf++) {
                    const uint32_t* bh = &bfh[nf >> 1][(nf & 1) * 2];
                    const uint32_t* bl = &bfl[nf >> 1][(nf & 1) * 2];
                    mma_bf16(acc[mf][nf], afh[mf], bh);
                    mma_bf16(acc[mf][nf], afh[mf], bl);
                    mma_bf16(acc[mf][nf], afl[mf], bh);
                }
        }
        __syncthreads();
    }

    // epilogue
    const float scale = (MODE == 0) ? QSCALE : 1.0f;
    __nv_bfloat16* Oh = (MODE == 0) ? g_qh : (MODE == 1) ? g_kh : g_vh;
    __nv_bfloat16* Ol = (MODE == 0) ? g_ql : (MODE == 1) ? g_kl : g_vl;
#pragma unroll
    for (int mf = 0; mf < 4; mf++) {
#pragma unroll
        for (int half = 0; half < 2; half++) {
            int m = m0 + wm * 64 + mf * 16 + g + half * 8;
#pragma unroll
            for (int nf = 0; nf < 4; nf++) {
                int n = n0 + wn * 32 + nf * 8 + 2 * tig;
                float v0 = acc[mf][nf][half * 2] * scale;
                float v1 = acc[mf][nf][half * 2 + 1] * scale;
                if (MODE == 3) {
                    float2 o = make_float2(v0 + bias[n], v1 + bias[n + 1]);
                    *(float2*)(out + (size_t)m * 1024 + n) = o;
                } else {
                    int b = m >> 11, ss = m & 2047;
                    int h = n >> 6, d = n & 63;
                    size_t addr = (((size_t)(b * 16 + h) * 2048) + ss) * 64 + d;
                    uint32_t hi, lo;
                    split2(v0, v1, hi, lo);
                    *(uint32_t*)(Oh + addr) = hi;
                    *(uint32_t*)(Ol + addr) = lo;
                }
            }
        }
    }
}

// ---------------- attention: mma.sync flash, no max tracking ----------------
// Q/K/V tiles: 128 rows x 64 bf16, row stride 144B (128B data + 16B pad), tile 18432B
// P tiles: 128 rows x 128 bf16, row stride 272B (256B data + 16B pad), tile 34816B
#define AT_TS 18432
#define AT_QH 0
#define AT_QL 18432
#define AT_KH 36864
#define AT_KL 55296
#define AT_VH 73728
#define AT_VL 92160
#define AT_PH 110592
#define AT_PL 145408
#define AT_RS 180224
#define AT_SB 180736
#define AT_SMEM 181760

__global__ void __launch_bounds__(256, 1)
attn_kernel(const float* __restrict__ bias_table)
{
    extern __shared__ char smem[];
    const uint32_t sb = su32(smem);
    float* rs = (float*)(smem + AT_RS);
    float* sbias = (float*)(smem + AT_SB);
    const int tid = threadIdx.x;
    const int lane = tid & 31, wid = tid >> 5;
    const int wm = wid >> 2, wn = wid & 3;
    const int g = lane >> 2, tig = lane & 3;
    const int bh = blockIdx.y;
    const int b = bh >> 4, h = bh & 15;
    const int q0 = blockIdx.x * 128;

    if (tid < 128) rs[tid] = 0.0f;

    // Q tiles hi/lo via cp.async: 2 tiles x 128 rows x 8 chunks = 2048 chunks
#pragma unroll
    for (int t = 0; t < 8; t++) {
        int vi = tid + t * 256;
        int half = vi >> 10;
        int row = (vi >> 3) & 127;
        int ch = vi & 7;
        const __nv_bfloat16* src = (half ? g_ql : g_qh)
            + ((size_t)bh * 2048 + q0 + row) * 64 + ch * 8;
        cpa16(sb + (half ? AT_QL : AT_QH) + row * 144 + ch * 16, src);
    }
    CP_COMMIT();

    float oacc[4][2][4];
#pragma unroll
    for (int i = 0; i < 4; i++)
#pragma unroll
        for (int j = 0; j < 2; j++)
#pragma unroll
            for (int e = 0; e < 4; e++) oacc[i][j][e] = 0.0f;
    float lsum[8];
#pragma unroll
    for (int i = 0; i < 8; i++) lsum[i] = 0.0f;

    const int d0 = wm * 64 - wn * 32 + g - 2 * tig + 127;

    for (int t = 0; t < 16; t++) {
        const int k0 = t * 128;
        // K/V tiles: 4 tiles x 1024 chunks
#pragma unroll
        for (int u = 0; u < 16; u++) {
            int vi = tid + u * 256;
            int tile = vi >> 10;          // 0 KH,1 KL,2 VH,3 VL
            int row = (vi >> 3) & 127;
            int ch = vi & 7;
            const __nv_bfloat16* src;
            if      (tile == 0) src = g_kh + ((size_t)bh * 2048 + k0 + row) * 64 + ch * 8;
            else if (tile == 1) src = g_kl + ((size_t)bh * 2048 + k0 + row) * 64 + ch * 8;
            else if (tile == 2) src = g_vh + ((size_t)bh * 2048 + k0 + row) * 64 + ch * 8;
            else                src = g_vl + ((size_t)bh * 2048 + k0 + row) * 64 + ch * 8;
            cpa16(sb + AT_KH + tile * AT_TS + row * 144 + ch * 16, src);
        }
        CP_COMMIT();
        if (tid < 255)
            sbias[tid] = bias_table[(size_t)(q0 - k0 + 1920 + tid) * 16 + h] * LOG2E;
        CP_WAIT0();
        __syncthreads();

        // ---- S = Q @ K^T (log2-scaled) ----
        float sacc[4][4][4];
#pragma unroll
        for (int i = 0; i < 4; i++)
#pragma unroll
            for (int j = 0; j < 4; j++)
#pragma unroll
                for (int e = 0; e < 4; e++) sacc[i][j][e] = 0.0f;
#pragma unroll
        for (int ks = 0; ks < 4; ks++) {
            uint32_t qfh[4][4], qfl[4][4], kfh[2][4], kfl[2][4];
#pragma unroll
            for (int mf = 0; mf < 4; mf++) {
                uint32_t a = sb + AT_QH + (uint32_t)(wm * 64 + mf * 16 + (lane & 15)) * 144
                           + (ks * 16 + (lane >> 4) * 8) * 2;
                ldsm4(qfh[mf], a);
                ldsm4(qfl[mf], a + AT_TS);
            }
#pragma unroll
            for (int g2 = 0; g2 < 2; g2++) {
                uint32_t a = sb + AT_KH
                           + (uint32_t)(wn * 32 + g2 * 16 + (lane & 7) + ((lane >> 4) << 3)) * 144
                           + (ks * 16 + ((lane >> 3) & 1) * 8) * 2;
                ldsm4(kfh[g2], a);
                ldsm4(kfl[g2], a + AT_TS);
            }
#pragma unroll
            for (int mf = 0; mf < 4; mf++)
#pragma unroll
                for (int nf = 0; nf < 4; nf++) {
                    const uint32_t* bhp = &kfh[nf >> 1][(nf & 1) * 2];
                    const uint32_t* blp = &kfl[nf >> 1][(nf & 1) * 2];
                    mma_bf16(sacc[mf][nf], qfh[mf], bhp);
                    mma_bf16(sacc[mf][nf], qfh[mf], blp);
                    mma_bf16(sacc[mf][nf], qfl[mf], bhp);
                }
        }

        // ---- P = 2^(S + bias), split hi/lo to SMEM, accumulate row sums ----
#pragma unroll
        for (int mf = 0; mf < 4; mf++) {
            int prow = wm * 64 + mf * 16 + g;
#pragma unroll
            for (int nf = 0; nf < 4; nf++) {
                float* c = sacc[mf][nf];
                int idx = d0 + mf * 16 - nf * 8;
                float p0 = ex2f(c[0] + sbias[idx]);
                float p1 = ex2f(c[1] + sbias[idx - 1]);
                float p2 = ex2f(c[2] + sbias[idx + 8]);
                float p3 = ex2f(c[3] + sbias[idx + 7]);
                lsum[mf * 2]     += p0 + p1;
                lsum[mf * 2 + 1] += p2 + p3;
                uint32_t hi, lo;
                uint32_t cb = (uint32_t)(wn * 32 + nf * 8 + 2 * tig) * 2;
                split2(p0, p1, hi, lo);
                *(uint32_t*)(smem + AT_PH + prow * 272 + cb) = hi;
                *(uint32_t*)(smem + AT_PL + prow * 272 + cb) = lo;
                split2(p2, p3, hi, lo);
                *(uint32_t*)(smem + AT_PH + (prow + 8) * 272 + cb) = hi;
                *(uint32_t*)(smem + AT_PL + (prow + 8) * 272 + cb) = lo;
            }
        }
        __syncthreads();

        // ---- O += P @ V ----
#pragma unroll
        for (int ks2 = 0; ks2 < 8; ks2++) {
            uint32_t pfh[4][4], pfl[4][4], vfh[4], vfl[4];
#pragma unroll
            for (int mf = 0; mf < 4; mf++) {
                uint32_t a = sb + AT_PH + (uint32_t)(wm * 64 + mf * 16 + (lane & 15)) * 272
                           + (ks2 * 16 + (lane >> 4) * 8) * 2;
                ldsm4(pfh[mf], a);
                ldsm4(pfl[mf], a + (AT_PL - AT_PH));
            }
            {
                uint32_t a = sb + AT_VH
                           + (uint32_t)(ks2 * 16 + (lane & 7) + ((lane >> 3) & 1) * 8) * 144
                           + (wn * 16 + ((lane >> 4) << 3)) * 2;
                ldsm4t(vfh, a);
                ldsm4t(vfl, a + AT_TS);
            }
#pragma unroll
            for (int mf = 0; mf < 4; mf++)
#pragma unroll
                for (int nf2 = 0; nf2 < 2; nf2++) {
                    mma_bf16(oacc[mf][nf2], pfh[mf], &vfh[nf2 * 2]);
                    mma_bf16(oacc[mf][nf2], pfh[mf], &vfl[nf2 * 2]);
                    mma_bf16(oacc[mf][nf2], pfl[mf], &vfh[nf2 * 2]);
                }
        }
        __syncthreads();
    }

    // ---- row-sum reduction ----
#pragma unroll
    for (int i = 0; i < 8; i++) {
        lsum[i] += __shfl_xor_sync(0xffffffffu, lsum[i], 1);
        lsum[i] += __shfl_xor_sync(0xffffffffu, lsum[i], 2);
    }
    if (tig == 0) {
#pragma unroll
        for (int mf = 0; mf < 4; mf++) {
            atomicAdd(&rs[wm * 64 + mf * 16 + g], lsum[mf * 2]);
            atomicAdd(&rs[wm * 64 + mf * 16 + g + 8], lsum[mf * 2 + 1]);
        }
    }
    __syncthreads();

    // ---- epilogue: ctx hi/lo ----
#pragma unroll
    for (int mf = 0; mf < 4; mf++) {
        int mlow = wm * 64 + mf * 16 + g;
        float inv0 = 1.0f / rs[mlow];
        float inv1 = 1.0f / rs[mlow + 8];
#pragma unroll
        for (int nf2 = 0; nf2 < 2; nf2++) {
            int d = wn * 16 + nf2 * 8 + 2 * tig;
            size_t a0 = (size_t)(b * 2048 + q0 + mlow) * 1024 + h * 64 + d;
            size_t a1 = (size_t)(b * 2048 + q0 + mlow + 8) * 1024 + h * 64 + d;
            uint32_t hi, lo;
            split2(oacc[mf][nf2][0] * inv0, oacc[mf][nf2][1] * inv0, hi, lo);
            *(uint32_t*)(g_ch + a0) = hi;
            *(uint32_t*)(g_cl + a0) = lo;
            split2(oacc[mf][nf2][2] * inv1, oacc[mf][nf2][3] * inv1, hi, lo);
            *(uint32_t*)(g_ch + a1) = hi;
            *(uint32_t*)(g_cl + a1) = lo;
        }
    }
}

// ---------------- launch ----------------
extern "C" void kernel_launch(void* const* d_in, const int* in_sizes, int n_in,
                              void* d_out, int out_size)
{
    const float* x  = (const float*)d_in[0];
    const float* Wq = (const float*)d_in[1];
    const float* Wk = (const float*)d_in[2];
    const float* Wv = (const float*)d_in[3];
    const float* Wo = (const float*)d_in[4];
    const float* bo = (const float*)d_in[5];
    const float* bt = (const float*)d_in[6];
    float* out = (float*)d_out;

    cudaFuncSetAttribute(proj_kernel<0>, cudaFuncAttributeMaxDynamicSharedMemorySize, 2 * PST);
    cudaFuncSetAttribute(proj_kernel<1>, cudaFuncAttributeMaxDynamicSharedMemorySize, 2 * PST);
    cudaFuncSetAttribute(proj_kernel<2>, cudaFuncAttributeMaxDynamicSharedMemorySize, 2 * PST);
    cudaFuncSetAttribute(proj_kernel<3>, cudaFuncAttributeMaxDynamicSharedMemorySize, 2 * PST);
    cudaFuncSetAttribute(attn_kernel,    cudaFuncAttributeMaxDynamicSharedMemorySize, AT_SMEM);

    split_x_kernel<<<2048, 256>>>(x);
    split_w_kernel<<<512, 256>>>(Wq, 0);
    split_w_kernel<<<512, 256>>>(Wk, 1);
    split_w_kernel<<<512, 256>>>(Wv, 2);
    split_w_kernel<<<512, 256>>>(Wo, 3);

    dim3 pg(64, 8);
    proj_kernel<0><<<pg, 256, 2 * PST>>>(nullptr, nullptr);
    proj_kernel<1><<<pg, 256, 2 * PST>>>(nullptr, nullptr);
    proj_kernel<2><<<pg, 256, 2 * PST>>>(nullptr, nullptr);

    attn_kernel<<<dim3(16, 64), 256, AT_SMEM>>>(bt);

    proj_kernel<3><<<pg, 256, 2 * PST>>>(bo, out);
}

// round 6
// speedup vs baseline: 2.8570x; 1.1272x over previous
#include <cuda_runtime.h>
#include <cuda_bf16.h>
#include <stdint.h>

#define D_MODEL 1024
#define NHEADS  16
#define HD      64
#define BATCH   4
#define SEQ     2048
#define BH      64
#define MTOK    8192
#define QSCALE  0.18033688011112042f   // 0.125 * log2(e)
#define LOG2E   1.4426950408889634f

// ---------------- scratch globals (allocation-free) ----------------
__device__ __nv_bfloat16 g_qh[8388608], g_ql[8388608];
__device__ __nv_bfloat16 g_kh[8388608], g_kl[8388608];
__device__ __nv_bfloat16 g_vh[8388608], g_vl[8388608];
__device__ __nv_bfloat16 g_xh[8388608], g_xl[8388608];
__device__ __nv_bfloat16 g_wh[4194304], g_wl[4194304];
__device__ __nv_bfloat16 g_ch[8388608], g_cl[8388608];

// ---------------- helpers ----------------
__device__ __forceinline__ uint32_t su32(const void* p) {
    uint32_t a;
    asm("{ .reg .u64 t; cvta.to.shared.u64 t, %1; cvt.u32.u64 %0, t; }" : "=r"(a) : "l"(p));
    return a;
}
__device__ __forceinline__ void cpa16(uint32_t dst, const void* src) {
    asm volatile("cp.async.cg.shared.global [%0], [%1], 16;" :: "r"(dst), "l"(src));
}
__device__ __forceinline__ void cpa4(uint32_t dst, const void* src) {
    asm volatile("cp.async.ca.shared.global [%0], [%1], 4;" :: "r"(dst), "l"(src));
}
#define CP_COMMIT() asm volatile("cp.async.commit_group;" ::: "memory")
#define CP_WAIT0()  asm volatile("cp.async.wait_group 0;" ::: "memory")
#define CP_WAIT1()  asm volatile("cp.async.wait_group 1;" ::: "memory")
#define CP_WAIT2()  asm volatile("cp.async.wait_group 2;" ::: "memory")

__device__ __forceinline__ void ldsm4(uint32_t* r, uint32_t addr) {
    asm volatile("ldmatrix.sync.aligned.m8n8.x4.shared.b16 {%0,%1,%2,%3}, [%4];"
                 : "=r"(r[0]), "=r"(r[1]), "=r"(r[2]), "=r"(r[3]) : "r"(addr));
}
__device__ __forceinline__ void ldsm4t(uint32_t* r, uint32_t addr) {
    asm volatile("ldmatrix.sync.aligned.m8n8.x4.trans.shared.b16 {%0,%1,%2,%3}, [%4];"
                 : "=r"(r[0]), "=r"(r[1]), "=r"(r[2]), "=r"(r[3]) : "r"(addr));
}
__device__ __forceinline__ void mma_bf16(float* c, const uint32_t* a, const uint32_t* b) {
    asm volatile("mma.sync.aligned.m16n8k16.row.col.f32.bf16.bf16.f32 "
                 "{%0,%1,%2,%3}, {%4,%5,%6,%7}, {%8,%9}, {%0,%1,%2,%3};"
                 : "+f"(c[0]), "+f"(c[1]), "+f"(c[2]), "+f"(c[3])
                 : "r"(a[0]), "r"(a[1]), "r"(a[2]), "r"(a[3]), "r"(b[0]), "r"(b[1]));
}
__device__ __forceinline__ float ex2f(float x) {
    float r; asm("ex2.approx.f32 %0, %1;" : "=f"(r) : "f"(x)); return r;
}
// split pair (v0,v1) -> packed bf16 hi pair + bf16 lo-residual pair
__device__ __forceinline__ void split2(float v0, float v1, uint32_t& hi, uint32_t& lo) {
    uint32_t b0 = __float_as_uint(v0), b1 = __float_as_uint(v1);
    uint32_t h0 = (b0 + 0x7FFFu + ((b0 >> 16) & 1u)) & 0xFFFF0000u;
    uint32_t h1 = (b1 + 0x7FFFu + ((b1 >> 16) & 1u)) & 0xFFFF0000u;
    hi = (h0 >> 16) | h1;
    float l0 = v0 - __uint_as_float(h0);
    float l1 = v1 - __uint_as_float(h1);
    asm("cvt.rn.bf16x2.f32 %0, %1, %2;" : "=r"(lo) : "f"(l1), "f"(l0));
}

// ---------------- prep: fp32 -> bf16 hi/lo ----------------
__global__ void split_x_kernel(const float* __restrict__ src) {
    for (size_t i = (size_t)blockIdx.x * blockDim.x + threadIdx.x; i < (size_t)MTOK * D_MODEL;
         i += (size_t)gridDim.x * blockDim.x) {
        float v = src[i];
        __nv_bfloat16 h = __float2bfloat16(v);
        g_xh[i] = h;
        g_xl[i] = __float2bfloat16(v - __bfloat162float(h));
    }
}
__global__ void split_w_kernel(const float* __restrict__ w0, const float* __restrict__ w1,
                               const float* __restrict__ w2, const float* __restrict__ w3) {
    int idx = blockIdx.y;
    const float* src = (idx == 0) ? w0 : (idx == 1) ? w1 : (idx == 2) ? w2 : w3;
    size_t off = (size_t)idx * 1048576;
    for (size_t i = (size_t)blockIdx.x * blockDim.x + threadIdx.x; i < 1048576;
         i += (size_t)gridDim.x * blockDim.x) {
        float v = src[i];
        __nv_bfloat16 h = __float2bfloat16(v);
        g_wh[off + i] = h;
        g_wl[off + i] = __float2bfloat16(v - __bfloat162float(h));
    }
}

// ---------------- projection GEMM: C[8192,1024] = A @ W^T, split bf16, mma.sync ----
// MODE 0:Q(scaled) 1:K 2:V 3:O(fp32 out + bias)
// stage: 4 tiles x [128 rows x 32 k-elems], row stride 80B; 3-stage pipeline
#define PST 40960

template<int MODE>
__global__ void __launch_bounds__(256, 1)
proj_kernel(const float* __restrict__ bias, float* __restrict__ out)
{
    extern __shared__ char smem[];
    const uint32_t sb = su32(smem);
    const int tid = threadIdx.x;
    const int lane = tid & 31, wid = tid >> 5;
    const int wm = wid >> 2, wn = wid & 3;
    const int g = lane >> 2, tig = lane & 3;
    const int m0 = blockIdx.x * 128, n0 = blockIdx.y * 128;

    const __nv_bfloat16* Ah = (MODE == 3) ? g_ch : g_xh;
    const __nv_bfloat16* Al = (MODE == 3) ? g_cl : g_xl;
    const __nv_bfloat16* Bh = g_wh + (size_t)MODE * 1048576;
    const __nv_bfloat16* Bl = g_wl + (size_t)MODE * 1048576;

    float acc[4][4][4];
#pragma unroll
    for (int i = 0; i < 4; i++)
#pragma unroll
        for (int j = 0; j < 4; j++)
#pragma unroll
            for (int e = 0; e < 4; e++) acc[i][j][e] = 0.0f;

    auto load_stage = [&](int kt, int buf) {
        uint32_t base = sb + buf * PST;
#pragma unroll
        for (int t = 0; t < 8; t++) {
            int vi = tid + t * 256;
            int tile = vi >> 9;
            int row = (vi >> 2) & 127;
            int ch = vi & 3;
            const __nv_bfloat16* src;
            if      (tile == 0) src = Ah + (size_t)(m0 + row) * 1024 + kt + ch * 8;
            else if (tile == 1) src = Al + (size_t)(m0 + row) * 1024 + kt + ch * 8;
            else if (tile == 2) src = Bh + (size_t)(n0 + row) * 1024 + kt + ch * 8;
            else                src = Bl + (size_t)(n0 + row) * 1024 + kt + ch * 8;
            cpa16(base + tile * 10240 + row * 80 + ch * 16, src);
        }
        CP_COMMIT();
    };

    load_stage(0, 0);
    load_stage(32, 1);
    for (int s = 0; s < 32; s++) {
        if (s < 30) load_stage((s + 2) * 32, (s + 2) % 3);
        int pend = 31 - s;
        if (pend >= 2) { CP_WAIT2(); } else if (pend == 1) { CP_WAIT1(); } else { CP_WAIT0(); }
        __syncthreads();
        uint32_t base = sb + (s % 3) * PST;
#pragma unroll
        for (int ks = 0; ks < 2; ks++) {
            uint32_t afh[4][4], afl[4][4], bfh[2][4], bfl[2][4];
#pragma unroll
            for (int mf = 0; mf < 4; mf++) {
                uint32_t a = base + (uint32_t)(wm * 64 + mf * 16 + (lane & 15)) * 80
                           + (ks * 16 + (lane >> 4) * 8) * 2;
                ldsm4(afh[mf], a);
                ldsm4(afl[mf], a + 10240);
            }
#pragma unroll
            for (int g2 = 0; g2 < 2; g2++) {
                uint32_t a = base + 20480
                           + (uint32_t)(wn * 32 + g2 * 16 + (lane & 7) + ((lane >> 4) << 3)) * 80
                           + (ks * 16 + ((lane >> 3) & 1) * 8) * 2;
                ldsm4(bfh[g2], a);
                ldsm4(bfl[g2], a + 10240);
            }
#pragma unroll
            for (int mf = 0; mf < 4; mf++)
#pragma unroll
                for (int nf = 0; nf < 4; nf++) {
                    const uint32_t* bh = &bfh[nf >> 1][(nf & 1) * 2];
                    const uint32_t* bl = &bfl[nf >> 1][(nf & 1) * 2];
                    mma_bf16(acc[mf][nf], afh[mf], bh);
                    mma_bf16(acc[mf][nf], afh[mf], bl);
                    mma_bf16(acc[mf][nf], afl[mf], bh);
                }
        }
        __syncthreads();
    }

    // epilogue
    const float scale = (MODE == 0) ? QSCALE : 1.0f;
    __nv_bfloat16* Oh = (MODE == 0) ? g_qh : (MODE == 1) ? g_kh : g_vh;
    __nv_bfloat16* Ol = (MODE == 0) ? g_ql : (MODE == 1) ? g_kl : g_vl;
#pragma unroll
    for (int mf = 0; mf < 4; mf++) {
#pragma unroll
        for (int half = 0; half < 2; half++) {
            int m = m0 + wm * 64 + mf * 16 + g + half * 8;
#pragma unroll
            for (int nf = 0; nf < 4; nf++) {
                int n = n0 + wn * 32 + nf * 8 + 2 * tig;
                float v0 = acc[mf][nf][half * 2] * scale;
                float v1 = acc[mf][nf][half * 2 + 1] * scale;
                if (MODE == 3) {
                    float2 o = make_float2(v0 + bias[n], v1 + bias[n + 1]);
                    *(float2*)(out + (size_t)m * 1024 + n) = o;
                } else {
                    int b = m >> 11, ss = m & 2047;
                    int h = n >> 6, d = n & 63;
                    size_t addr = (((size_t)(b * 16 + h) * 2048) + ss) * 64 + d;
                    uint32_t hi, lo;
                    split2(v0, v1, hi, lo);
                    *(uint32_t*)(Oh + addr) = hi;
                    *(uint32_t*)(Ol + addr) = lo;
                }
            }
        }
    }
}

// ---------------- attention: FA2-style register-P, double-buffered K/V ----------------
// 8 warps x 16 q-rows. Q/K/V tiles: 128 x 64 bf16, stride 144B, tile 18432B.
// SMEM: QH 0, QL 18432; KV stages at 36864 + stage*73728 (KH,KL,VH,VL);
//       bias at 184320 + stage*1024. Total 186368.
#define AT_TS  18432
#define AT_QH  0
#define AT_QL  18432
#define AT_KV  36864
#define AT_KVS 73728
#define AT_SB  184320
#define AT_SMEM 186368

__global__ void __launch_bounds__(256, 1)
attn_kernel(const float* __restrict__ bias_table)
{
    extern __shared__ char smem[];
    const uint32_t sb = su32(smem);
    const int tid = threadIdx.x;
    const int lane = tid & 31, w = tid >> 5;
    const int g = lane >> 2, tig = lane & 3;
    const int bh = blockIdx.y;
    const int b = bh >> 4, h = bh & 15;
    const int q0 = blockIdx.x * 128;

    // Q tiles hi/lo
#pragma unroll
    for (int t2 = 0; t2 < 8; t2++) {
        int vi = tid + t2 * 256;
        int half = vi >> 10;
        int row = (vi >> 3) & 127;
        int ch = vi & 7;
        const __nv_bfloat16* src = (half ? g_ql : g_qh)
            + ((size_t)bh * 2048 + q0 + row) * 64 + ch * 8;
        cpa16(sb + (half ? AT_QL : AT_QH) + row * 144 + ch * 16, src);
    }

    auto issue_kv = [&](int buf, int k0) {
        uint32_t base = sb + AT_KV + buf * AT_KVS;
#pragma unroll
        for (int u = 0; u < 16; u++) {
            int vi = tid + u * 256;
            int tile = vi >> 10;          // 0 KH,1 KL,2 VH,3 VL
            int row = (vi >> 3) & 127;
            int ch = vi & 7;
            const __nv_bfloat16* src;
            if      (tile == 0) src = g_kh + ((size_t)bh * 2048 + k0 + row) * 64 + ch * 8;
            else if (tile == 1) src = g_kl + ((size_t)bh * 2048 + k0 + row) * 64 + ch * 8;
            else if (tile == 2) src = g_vh + ((size_t)bh * 2048 + k0 + row) * 64 + ch * 8;
            else                src = g_vl + ((size_t)bh * 2048 + k0 + row) * 64 + ch * 8;
            cpa16(base + tile * AT_TS + row * 144 + ch * 16, src);
        }
        if (tid < 255)
            cpa4(sb + AT_SB + buf * 1024 + tid * 4,
                 bias_table + (size_t)(q0 - k0 + 1920 + tid) * 16 + h);
    };

    issue_kv(0, 0);
    CP_COMMIT();   // group: Q + KV0

    float oacc[8][4];
#pragma unroll
    for (int i = 0; i < 8; i++)
#pragma unroll
        for (int e = 0; e < 4; e++) oacc[i][e] = 0.0f;
    float lsumA = 0.0f, lsumB = 0.0f;

    const int d0 = w * 16 + g - 2 * tig + 127;

    for (int t = 0; t < 16; t++) {
        if (t < 15) { issue_kv((t + 1) & 1, (t + 1) * 128); CP_COMMIT(); CP_WAIT1(); }
        else CP_WAIT0();
        __syncthreads();

        const uint32_t kvb = sb + AT_KV + (t & 1) * AT_KVS;
        const float* sbias = (const float*)(smem + AT_SB + (t & 1) * 1024);

        // ---- S = Q @ K^T (log2-scaled), full 128 cols per warp ----
        float sacc[16][4];
#pragma unroll
        for (int i = 0; i < 16; i++)
#pragma unroll
            for (int e = 0; e < 4; e++) sacc[i][e] = 0.0f;
#pragma unroll
        for (int ks = 0; ks < 4; ks++) {
            uint32_t qfh[4], qfl[4];
            {
                uint32_t a = sb + AT_QH + (uint32_t)(w * 16 + (lane & 15)) * 144
                           + (ks * 16 + (lane >> 4) * 8) * 2;
                ldsm4(qfh, a);
                ldsm4(qfl, a + AT_TS);
            }
#pragma unroll
            for (int half2 = 0; half2 < 2; half2++) {
                uint32_t kfh[4][4], kfl[4][4];
#pragma unroll
                for (int g2 = 0; g2 < 4; g2++) {
                    uint32_t a = kvb
                        + (uint32_t)((half2 * 4 + g2) * 16 + (lane & 7) + ((lane >> 4) << 3)) * 144
                        + (ks * 16 + ((lane >> 3) & 1) * 8) * 2;
                    ldsm4(kfh[g2], a);
                    ldsm4(kfl[g2], a + AT_TS);
                }
#pragma unroll
                for (int nf2 = 0; nf2 < 8; nf2++) {
                    float* c = sacc[half2 * 8 + nf2];
                    const uint32_t* bhp = &kfh[nf2 >> 1][(nf2 & 1) * 2];
                    const uint32_t* blp = &kfl[nf2 >> 1][(nf2 & 1) * 2];
                    mma_bf16(c, qfh, bhp);
                    mma_bf16(c, qfh, blp);
                    mma_bf16(c, qfl, bhp);
                }
            }
        }

        // ---- P = 2^(S + bias*log2e) in registers: C-frag -> A-frag identity ----
        uint32_t pfh[8][4], pfl[8][4];
#pragma unroll
        for (int ks2 = 0; ks2 < 8; ks2++) {
#pragma unroll
            for (int j = 0; j < 2; j++) {
                int nf = 2 * ks2 + j;
                float* c = sacc[nf];
                int idx = d0 - nf * 8;
                float p0 = ex2f(fmaf(sbias[idx],     LOG2E, c[0]));
                float p1 = ex2f(fmaf(sbias[idx - 1], LOG2E, c[1]));
                float p2 = ex2f(fmaf(sbias[idx + 8], LOG2E, c[2]));
                float p3 = ex2f(fmaf(sbias[idx + 7], LOG2E, c[3]));
                lsumA += p0 + p1;
                lsumB += p2 + p3;
                split2(p0, p1, pfh[ks2][j * 2 + 0], pfl[ks2][j * 2 + 0]);
                split2(p2, p3, pfh[ks2][j * 2 + 1], pfl[ks2][j * 2 + 1]);
            }
        }

        // ---- O += P @ V ----
        const uint32_t vb = kvb + 2 * AT_TS;
#pragma unroll
        for (int ks2 = 0; ks2 < 8; ks2++) {
            uint32_t vfh[4][4], vfl[4][4];
#pragma unroll
            for (int dblk = 0; dblk < 4; dblk++) {
                uint32_t a = vb
                    + (uint32_t)(ks2 * 16 + (lane & 7) + ((lane >> 3) & 1) * 8) * 144
                    + (dblk * 16 + ((lane >> 4) << 3)) * 2;
                ldsm4t(vfh[dblk], a);
                ldsm4t(vfl[dblk], a + AT_TS);
            }
#pragma unroll
            for (int dblk = 0; dblk < 4; dblk++)
#pragma unroll
                for (int sub = 0; sub < 2; sub++) {
                    float* o = oacc[dblk * 2 + sub];
                    mma_bf16(o, pfh[ks2], &vfh[dblk][sub * 2]);
                    mma_bf16(o, pfh[ks2], &vfl[dblk][sub * 2]);
                    mma_bf16(o, pfl[ks2], &vfh[dblk][sub * 2]);
                }
        }
        __syncthreads();
    }

    // ---- row-sum reduce within quad, epilogue ----
    lsumA += __shfl_xor_sync(0xffffffffu, lsumA, 1);
    lsumA += __shfl_xor_sync(0xffffffffu, lsumA, 2);
    lsumB += __shfl_xor_sync(0xffffffffu, lsumB, 1);
    lsumB += __shfl_xor_sync(0xffffffffu, lsumB, 2);
    const float inv0 = 1.0f / lsumA;
    const float inv1 = 1.0f / lsumB;
    const int row0 = q0 + w * 16 + g;
    const size_t base0 = (size_t)(b * 2048 + row0) * 1024 + h * 64;
    const size_t base1 = (size_t)(b * 2048 + row0 + 8) * 1024 + h * 64;
#pragma unroll
    for (int nfd = 0; nfd < 8; nfd++) {
        int d = nfd * 8 + 2 * tig;
        uint32_t hi, lo;
        split2(oacc[nfd][0] * inv0, oacc[nfd][1] * inv0, hi, lo);
        *(uint32_t*)(g_ch + base0 + d) = hi;
        *(uint32_t*)(g_cl + base0 + d) = lo;
        split2(oacc[nfd][2] * inv1, oacc[nfd][3] * inv1, hi, lo);
        *(uint32_t*)(g_ch + base1 + d) = hi;
        *(uint32_t*)(g_cl + base1 + d) = lo;
    }
}

// ---------------- launch ----------------
extern "C" void kernel_launch(void* const* d_in, const int* in_sizes, int n_in,
                              void* d_out, int out_size)
{
    const float* x  = (const float*)d_in[0];
    const float* Wq = (const float*)d_in[1];
    const float* Wk = (const float*)d_in[2];
    const float* Wv = (const float*)d_in[3];
    const float* Wo = (const float*)d_in[4];
    const float* bo = (const float*)d_in[5];
    const float* bt = (const float*)d_in[6];
    float* out = (float*)d_out;

    cudaFuncSetAttribute(proj_kernel<0>, cudaFuncAttributeMaxDynamicSharedMemorySize, 3 * PST);
    cudaFuncSetAttribute(proj_kernel<1>, cudaFuncAttributeMaxDynamicSharedMemorySize, 3 * PST);
    cudaFuncSetAttribute(proj_kernel<2>, cudaFuncAttributeMaxDynamicSharedMemorySize, 3 * PST);
    cudaFuncSetAttribute(proj_kernel<3>, cudaFuncAttributeMaxDynamicSharedMemorySize, 3 * PST);
    cudaFuncSetAttribute(attn_kernel,    cudaFuncAttributeMaxDynamicSharedMemorySize, AT_SMEM);

    split_x_kernel<<<2048, 256>>>(x);
    split_w_kernel<<<dim3(256, 4), 256>>>(Wq, Wk, Wv, Wo);

    dim3 pg(64, 8);
    proj_kernel<0><<<pg, 256, 3 * PST>>>(nullptr, nullptr);
    proj_kernel<1><<<pg, 256, 3 * PST>>>(nullptr, nullptr);
    proj_kernel<2><<<pg, 256, 3 * PST>>>(nullptr, nullptr);

    attn_kernel<<<dim3(16, 64), 256, AT_SMEM>>>(bt);

    proj_kernel<3><<<pg, 256, 3 * PST>>>(bo, out);
}

// round 7
// speedup vs baseline: 3.2405x; 1.1342x over previous
#include <cuda_runtime.h>
#include <cuda_bf16.h>
#include <stdint.h>

#define D_MODEL 1024
#define NHEADS  16
#define HD      64
#define BATCH   4
#define SEQ     2048
#define BH      64
#define MTOK    8192
#define QSCALE  0.18033688011112042f   // 0.125 * log2(e)
#define LOG2E   1.4426950408889634f

// ---------------- scratch globals (allocation-free) ----------------
__device__ __nv_bfloat16 g_qh[8388608], g_ql[8388608];
__device__ __nv_bfloat16 g_kh[8388608], g_kl[8388608];
__device__ __nv_bfloat16 g_vh[8388608], g_vl[8388608];
__device__ __nv_bfloat16 g_xh[8388608], g_xl[8388608];
__device__ __nv_bfloat16 g_wh[4194304], g_wl[4194304];
__device__ __nv_bfloat16 g_ch[8388608], g_cl[8388608];

// ---------------- helpers ----------------
__device__ __forceinline__ uint32_t su32(const void* p) {
    uint32_t a;
    asm("{ .reg .u64 t; cvta.to.shared.u64 t, %1; cvt.u32.u64 %0, t; }" : "=r"(a) : "l"(p));
    return a;
}
__device__ __forceinline__ void cpa16(uint32_t dst, const void* src) {
    asm volatile("cp.async.cg.shared.global [%0], [%1], 16;" :: "r"(dst), "l"(src));
}
__device__ __forceinline__ void cpa4(uint32_t dst, const void* src) {
    asm volatile("cp.async.ca.shared.global [%0], [%1], 4;" :: "r"(dst), "l"(src));
}
#define CP_COMMIT() asm volatile("cp.async.commit_group;" ::: "memory")
#define CP_WAIT0()  asm volatile("cp.async.wait_group 0;" ::: "memory")
#define CP_WAIT1()  asm volatile("cp.async.wait_group 1;" ::: "memory")

__device__ __forceinline__ void ldsm4(uint32_t* r, uint32_t addr) {
    asm volatile("ldmatrix.sync.aligned.m8n8.x4.shared.b16 {%0,%1,%2,%3}, [%4];"
                 : "=r"(r[0]), "=r"(r[1]), "=r"(r[2]), "=r"(r[3]) : "r"(addr));
}
__device__ __forceinline__ void ldsm4t(uint32_t* r, uint32_t addr) {
    asm volatile("ldmatrix.sync.aligned.m8n8.x4.trans.shared.b16 {%0,%1,%2,%3}, [%4];"
                 : "=r"(r[0]), "=r"(r[1]), "=r"(r[2]), "=r"(r[3]) : "r"(addr));
}
__device__ __forceinline__ void mma_bf16(float* c, const uint32_t* a, const uint32_t* b) {
    asm volatile("mma.sync.aligned.m16n8k16.row.col.f32.bf16.bf16.f32 "
                 "{%0,%1,%2,%3}, {%4,%5,%6,%7}, {%8,%9}, {%0,%1,%2,%3};"
                 : "+f"(c[0]), "+f"(c[1]), "+f"(c[2]), "+f"(c[3])
                 : "r"(a[0]), "r"(a[1]), "r"(a[2]), "r"(a[3]), "r"(b[0]), "r"(b[1]));
}
__device__ __forceinline__ float ex2f(float x) {
    float r; asm("ex2.approx.f32 %0, %1;" : "=f"(r) : "f"(x)); return r;
}
// split pair (v0,v1) -> packed bf16 hi pair + bf16 lo-residual pair
__device__ __forceinline__ void split2(float v0, float v1, uint32_t& hi, uint32_t& lo) {
    uint32_t b0 = __float_as_uint(v0), b1 = __float_as_uint(v1);
    uint32_t h0 = (b0 + 0x7FFFu + ((b0 >> 16) & 1u)) & 0xFFFF0000u;
    uint32_t h1 = (b1 + 0x7FFFu + ((b1 >> 16) & 1u)) & 0xFFFF0000u;
    hi = (h0 >> 16) | h1;
    float l0 = v0 - __uint_as_float(h0);
    float l1 = v1 - __uint_as_float(h1);
    asm("cvt.rn.bf16x2.f32 %0, %1, %2;" : "=r"(lo) : "f"(l1), "f"(l0));
}

// ---------------- prep: fp32 -> bf16 hi/lo ----------------
__global__ void split_x_kernel(const float* __restrict__ src) {
    for (size_t i = (size_t)blockIdx.x * blockDim.x + threadIdx.x; i < (size_t)MTOK * D_MODEL;
         i += (size_t)gridDim.x * blockDim.x) {
        float v = src[i];
        __nv_bfloat16 h = __float2bfloat16(v);
        g_xh[i] = h;
        g_xl[i] = __float2bfloat16(v - __bfloat162float(h));
    }
}
__global__ void split_w_kernel(const float* __restrict__ w0, const float* __restrict__ w1,
                               const float* __restrict__ w2, const float* __restrict__ w3) {
    int idx = blockIdx.y;
    const float* src = (idx == 0) ? w0 : (idx == 1) ? w1 : (idx == 2) ? w2 : w3;
    size_t off = (size_t)idx * 1048576;
    for (size_t i = (size_t)blockIdx.x * blockDim.x + threadIdx.x; i < 1048576;
         i += (size_t)gridDim.x * blockDim.x) {
        float v = src[i];
        __nv_bfloat16 h = __float2bfloat16(v);
        g_wh[off + i] = h;
        g_wl[off + i] = __float2bfloat16(v - __bfloat162float(h));
    }
}

// ---------------- projection GEMM: C[8192,1024] = A @ W^T, split bf16, mma.sync ----
// OPROJ=0: QKV merged via blockIdx.z (0:Q scaled, 1:K, 2:V) -> hi/lo scratch
// OPROJ=1: O projection (g_c @ Wo^T + bias) -> fp32 out
// stage: 4 tiles x [128 rows x 32 k-elems], row stride 80B; 2-stage pipeline, 2 CTAs/SM
#define PST 40960

template<int OPROJ>
__global__ void __launch_bounds__(256, 2)
proj_kernel(const float* __restrict__ bias, float* __restrict__ out)
{
    extern __shared__ char smem[];
    const uint32_t sb = su32(smem);
    const int tid = threadIdx.x;
    const int lane = tid & 31, wid = tid >> 5;
    const int wm = wid >> 2, wn = wid & 3;
    const int g = lane >> 2, tig = lane & 3;
    const int m0 = blockIdx.x * 128, n0 = blockIdx.y * 128;
    const int mode = OPROJ ? 3 : (int)blockIdx.z;

    const __nv_bfloat16* Ah = OPROJ ? g_ch : g_xh;
    const __nv_bfloat16* Al = OPROJ ? g_cl : g_xl;
    const __nv_bfloat16* Bh = g_wh + (size_t)mode * 1048576;
    const __nv_bfloat16* Bl = g_wl + (size_t)mode * 1048576;

    float acc[4][4][4];
#pragma unroll
    for (int i = 0; i < 4; i++)
#pragma unroll
        for (int j = 0; j < 4; j++)
#pragma unroll
            for (int e = 0; e < 4; e++) acc[i][j][e] = 0.0f;

    auto load_stage = [&](int kt, int buf) {
        uint32_t base = sb + buf * PST;
#pragma unroll
        for (int t = 0; t < 8; t++) {
            int vi = tid + t * 256;
            int tile = vi >> 9;
            int row = (vi >> 2) & 127;
            int ch = vi & 3;
            const __nv_bfloat16* src;
            if      (tile == 0) src = Ah + (size_t)(m0 + row) * 1024 + kt + ch * 8;
            else if (tile == 1) src = Al + (size_t)(m0 + row) * 1024 + kt + ch * 8;
            else if (tile == 2) src = Bh + (size_t)(n0 + row) * 1024 + kt + ch * 8;
            else                src = Bl + (size_t)(n0 + row) * 1024 + kt + ch * 8;
            cpa16(base + tile * 10240 + row * 80 + ch * 16, src);
        }
        CP_COMMIT();
    };

    load_stage(0, 0);
    for (int s = 0; s < 32; s++) {
        if (s < 31) { load_stage((s + 1) * 32, (s + 1) & 1); CP_WAIT1(); }
        else CP_WAIT0();
        __syncthreads();
        uint32_t base = sb + (s & 1) * PST;
#pragma unroll
        for (int ks = 0; ks < 2; ks++) {
            uint32_t afh[4][4], afl[4][4];
#pragma unroll
            for (int mf = 0; mf < 4; mf++) {
                uint32_t a = base + (uint32_t)(wm * 64 + mf * 16 + (lane & 15)) * 80
                           + (ks * 16 + (lane >> 4) * 8) * 2;
                ldsm4(afh[mf], a);
                ldsm4(afl[mf], a + 10240);
            }
#pragma unroll
            for (int g2 = 0; g2 < 2; g2++) {
                uint32_t bfh[4], bfl[4];
                uint32_t a = base + 20480
                           + (uint32_t)(wn * 32 + g2 * 16 + (lane & 7) + ((lane >> 4) << 3)) * 80
                           + (ks * 16 + ((lane >> 3) & 1) * 8) * 2;
                ldsm4(bfh, a);
                ldsm4(bfl, a + 10240);
#pragma unroll
                for (int mf = 0; mf < 4; mf++)
#pragma unroll
                    for (int j = 0; j < 2; j++) {
                        float* c = acc[mf][g2 * 2 + j];
                        mma_bf16(c, afh[mf], &bfh[j * 2]);
                        mma_bf16(c, afh[mf], &bfl[j * 2]);
                        mma_bf16(c, afl[mf], &bfh[j * 2]);
                    }
            }
        }
        __syncthreads();
    }

    // epilogue
    const float scale = (mode == 0) ? QSCALE : 1.0f;
    __nv_bfloat16* Oh = (mode == 0) ? g_qh : (mode == 1) ? g_kh : g_vh;
    __nv_bfloat16* Ol = (mode == 0) ? g_ql : (mode == 1) ? g_kl : g_vl;
#pragma unroll
    for (int mf = 0; mf < 4; mf++) {
#pragma unroll
        for (int half = 0; half < 2; half++) {
            int m = m0 + wm * 64 + mf * 16 + g + half * 8;
#pragma unroll
            for (int nf = 0; nf < 4; nf++) {
                int n = n0 + wn * 32 + nf * 8 + 2 * tig;
                float v0 = acc[mf][nf][half * 2] * scale;
                float v1 = acc[mf][nf][half * 2 + 1] * scale;
                if (OPROJ) {
                    float2 o = make_float2(v0 + bias[n], v1 + bias[n + 1]);
                    *(float2*)(out + (size_t)m * 1024 + n) = o;
                } else {
                    int b = m >> 11, ss = m & 2047;
                    int h = n >> 6, d = n & 63;
                    size_t addr = (((size_t)(b * 16 + h) * 2048) + ss) * 64 + d;
                    uint32_t hi, lo;
                    split2(v0, v1, hi, lo);
                    *(uint32_t*)(Oh + addr) = hi;
                    *(uint32_t*)(Ol + addr) = lo;
                }
            }
        }
    }
}

// ---------------- attention: FA2-style register-P, double-buffered K/V ----------------
// 8 warps x 16 q-rows. Q/K/V tiles: 128 x 64 bf16, stride 144B, tile 18432B.
// SMEM: QH 0, QL 18432; KV stages at 36864 + stage*73728 (KH,KL,VH,VL);
//       bias at 184320 + stage*1024. Total 186368.
#define AT_TS  18432
#define AT_QH  0
#define AT_QL  18432
#define AT_KV  36864
#define AT_KVS 73728
#define AT_SB  184320
#define AT_SMEM 186368

__global__ void __launch_bounds__(256, 1)
attn_kernel(const float* __restrict__ bias_table)
{
    extern __shared__ char smem[];
    const uint32_t sb = su32(smem);
    const int tid = threadIdx.x;
    const int lane = tid & 31, w = tid >> 5;
    const int g = lane >> 2, tig = lane & 3;
    const int bh = blockIdx.y;
    const int b = bh >> 4, h = bh & 15;
    const int q0 = blockIdx.x * 128;

    // Q tiles hi/lo
#pragma unroll
    for (int t2 = 0; t2 < 8; t2++) {
        int vi = tid + t2 * 256;
        int half = vi >> 10;
        int row = (vi >> 3) & 127;
        int ch = vi & 7;
        const __nv_bfloat16* src = (half ? g_ql : g_qh)
            + ((size_t)bh * 2048 + q0 + row) * 64 + ch * 8;
        cpa16(sb + (half ? AT_QL : AT_QH) + row * 144 + ch * 16, src);
    }

    auto issue_kv = [&](int buf, int k0) {
        uint32_t base = sb + AT_KV + buf * AT_KVS;
#pragma unroll
        for (int u = 0; u < 16; u++) {
            int vi = tid + u * 256;
            int tile = vi >> 10;          // 0 KH,1 KL,2 VH,3 VL
            int row = (vi >> 3) & 127;
            int ch = vi & 7;
            const __nv_bfloat16* src;
            if      (tile == 0) src = g_kh + ((size_t)bh * 2048 + k0 + row) * 64 + ch * 8;
            else if (tile == 1) src = g_kl + ((size_t)bh * 2048 + k0 + row) * 64 + ch * 8;
            else if (tile == 2) src = g_vh + ((size_t)bh * 2048 + k0 + row) * 64 + ch * 8;
            else                src = g_vl + ((size_t)bh * 2048 + k0 + row) * 64 + ch * 8;
            cpa16(base + tile * AT_TS + row * 144 + ch * 16, src);
        }
        if (tid < 255)
            cpa4(sb + AT_SB + buf * 1024 + tid * 4,
                 bias_table + (size_t)(q0 - k0 + 1920 + tid) * 16 + h);
    };

    issue_kv(0, 0);
    CP_COMMIT();   // group: Q + KV0

    float oacc[8][4];
#pragma unroll
    for (int i = 0; i < 8; i++)
#pragma unroll
        for (int e = 0; e < 4; e++) oacc[i][e] = 0.0f;
    float lsumA = 0.0f, lsumB = 0.0f;

    uint32_t qfh[4][4], qfl[4][4];   // Q fragments, loaded once at t==0

    const int d0 = w * 16 + g - 2 * tig + 127;

    for (int t = 0; t < 16; t++) {
        if (t < 15) { issue_kv((t + 1) & 1, (t + 1) * 128); CP_COMMIT(); CP_WAIT1(); }
        else CP_WAIT0();
        __syncthreads();

        if (t == 0) {
#pragma unroll
            for (int ks = 0; ks < 4; ks++) {
                uint32_t a = sb + AT_QH + (uint32_t)(w * 16 + (lane & 15)) * 144
                           + (ks * 16 + (lane >> 4) * 8) * 2;
                ldsm4(qfh[ks], a);
                ldsm4(qfl[ks], a + AT_TS);
            }
        }

        const uint32_t kvb = sb + AT_KV + (t & 1) * AT_KVS;
        const float* sbias = (const float*)(smem + AT_SB + (t & 1) * 1024);

        // ---- S = Q @ K^T (log2-scaled), full 128 cols per warp ----
        float sacc[16][4];
#pragma unroll
        for (int i = 0; i < 16; i++)
#pragma unroll
            for (int e = 0; e < 4; e++) sacc[i][e] = 0.0f;
#pragma unroll
        for (int ks = 0; ks < 4; ks++) {
#pragma unroll
            for (int half2 = 0; half2 < 2; half2++) {
                uint32_t kfh[4][4], kfl[4][4];
#pragma unroll
                for (int g2 = 0; g2 < 4; g2++) {
                    uint32_t a = kvb
                        + (uint32_t)((half2 * 4 + g2) * 16 + (lane & 7) + ((lane >> 4) << 3)) * 144
                        + (ks * 16 + ((lane >> 3) & 1) * 8) * 2;
                    ldsm4(kfh[g2], a);
                    ldsm4(kfl[g2], a + AT_TS);
                }
#pragma unroll
                for (int nf2 = 0; nf2 < 8; nf2++) {
                    float* c = sacc[half2 * 8 + nf2];
                    const uint32_t* bhp = &kfh[nf2 >> 1][(nf2 & 1) * 2];
                    const uint32_t* blp = &kfl[nf2 >> 1][(nf2 & 1) * 2];
                    mma_bf16(c, qfh[ks], bhp);
                    mma_bf16(c, qfh[ks], blp);
                    mma_bf16(c, qfl[ks], bhp);
                }
            }
        }

        // ---- P = 2^(S + bias*log2e) in registers: C-frag -> A-frag identity ----
        uint32_t pfh[8][4], pfl[8][4];
#pragma unroll
        for (int ks2 = 0; ks2 < 8; ks2++) {
#pragma unroll
            for (int j = 0; j < 2; j++) {
                int nf = 2 * ks2 + j;
                float* c = sacc[nf];
                int idx = d0 - nf * 8;
                float p0 = ex2f(fmaf(sbias[idx],     LOG2E, c[0]));
                float p1 = ex2f(fmaf(sbias[idx - 1], LOG2E, c[1]));
                float p2 = ex2f(fmaf(sbias[idx + 8], LOG2E, c[2]));
                float p3 = ex2f(fmaf(sbias[idx + 7], LOG2E, c[3]));
                lsumA += p0 + p1;
                lsumB += p2 + p3;
                split2(p0, p1, pfh[ks2][j * 2 + 0], pfl[ks2][j * 2 + 0]);
                split2(p2, p3, pfh[ks2][j * 2 + 1], pfl[ks2][j * 2 + 1]);
            }
        }

        // ---- O += P @ V ----
        const uint32_t vb = kvb + 2 * AT_TS;
#pragma unroll
        for (int ks2 = 0; ks2 < 8; ks2++) {
            uint32_t vfh[4][4], vfl[4][4];
#pragma unroll
            for (int dblk = 0; dblk < 4; dblk++) {
                uint32_t a = vb
                    + (uint32_t)(ks2 * 16 + (lane & 7) + ((lane >> 3) & 1) * 8) * 144
                    + (dblk * 16 + ((lane >> 4) << 3)) * 2;
                ldsm4t(vfh[dblk], a);
                ldsm4t(vfl[dblk], a + AT_TS);
            }
#pragma unroll
            for (int dblk = 0; dblk < 4; dblk++)
#pragma unroll
                for (int sub = 0; sub < 2; sub++) {
                    float* o = oacc[dblk * 2 + sub];
                    mma_bf16(o, pfh[ks2], &vfh[dblk][sub * 2]);
                    mma_bf16(o, pfh[ks2], &vfl[dblk][sub * 2]);
                    mma_bf16(o, pfl[ks2], &vfh[dblk][sub * 2]);
                }
        }
        __syncthreads();
    }

    // ---- row-sum reduce within quad, epilogue ----
    lsumA += __shfl_xor_sync(0xffffffffu, lsumA, 1);
    lsumA += __shfl_xor_sync(0xffffffffu, lsumA, 2);
    lsumB += __shfl_xor_sync(0xffffffffu, lsumB, 1);
    lsumB += __shfl_xor_sync(0xffffffffu, lsumB, 2);
    const float inv0 = 1.0f / lsumA;
    const float inv1 = 1.0f / lsumB;
    const int row0 = q0 + w * 16 + g;
    const size_t base0 = (size_t)(b * 2048 + row0) * 1024 + h * 64;
    const size_t base1 = (size_t)(b * 2048 + row0 + 8) * 1024 + h * 64;
#pragma unroll
    for (int nfd = 0; nfd < 8; nfd++) {
        int d = nfd * 8 + 2 * tig;
        uint32_t hi, lo;
        split2(oacc[nfd][0] * inv0, oacc[nfd][1] * inv0, hi, lo);
        *(uint32_t*)(g_ch + base0 + d) = hi;
        *(uint32_t*)(g_cl + base0 + d) = lo;
        split2(oacc[nfd][2] * inv1, oacc[nfd][3] * inv1, hi, lo);
        *(uint32_t*)(g_ch + base1 + d) = hi;
        *(uint32_t*)(g_cl + base1 + d) = lo;
    }
}

// ---------------- launch ----------------
extern "C" void kernel_launch(void* const* d_in, const int* in_sizes, int n_in,
                              void* d_out, int out_size)
{
    const float* x  = (const float*)d_in[0];
    const float* Wq = (const float*)d_in[1];
    const float* Wk = (const float*)d_in[2];
    const float* Wv = (const float*)d_in[3];
    const float* Wo = (const float*)d_in[4];
    const float* bo = (const float*)d_in[5];
    const float* bt = (const float*)d_in[6];
    float* out = (float*)d_out;

    cudaFuncSetAttribute(proj_kernel<0>, cudaFuncAttributeMaxDynamicSharedMemorySize, 2 * PST);
    cudaFuncSetAttribute(proj_kernel<1>, cudaFuncAttributeMaxDynamicSharedMemorySize, 2 * PST);
    cudaFuncSetAttribute(attn_kernel,    cudaFuncAttributeMaxDynamicSharedMemorySize, AT_SMEM);

    split_x_kernel<<<2048, 256>>>(x);
    split_w_kernel<<<dim3(256, 4), 256>>>(Wq, Wk, Wv, Wo);

    proj_kernel<0><<<dim3(64, 8, 3), 256, 2 * PST>>>(nullptr, nullptr);

    attn_kernel<<<dim3(16, 64), 256, AT_SMEM>>>(bt);

    proj_kernel<1><<<dim3(64, 8), 256, 2 * PST>>>(bo, out);
}

// round 8
// speedup vs baseline: 3.2645x; 1.0074x over previous
#include <cuda_runtime.h>
#include <cuda_bf16.h>
#include <stdint.h>

#define D_MODEL 1024
#define NHEADS  16
#define HD      64
#define BATCH   4
#define SEQ     2048
#define BH      64
#define MTOK    8192
#define QSCALE  0.18033688011112042f   // 0.125 * log2(e)
#define LOG2E   1.4426950408889634f

// ---------------- scratch globals (allocation-free) ----------------
__device__ __nv_bfloat16 g_qh[8388608], g_ql[8388608];
__device__ __nv_bfloat16 g_kh[8388608], g_kl[8388608];
__device__ __nv_bfloat16 g_vh[8388608], g_vl[8388608];
__device__ __nv_bfloat16 g_xh[8388608], g_xl[8388608];
__device__ __nv_bfloat16 g_wh[4194304], g_wl[4194304];
__device__ __nv_bfloat16 g_ch[8388608], g_cl[8388608];

// ---------------- helpers ----------------
__device__ __forceinline__ uint32_t su32(const void* p) {
    uint32_t a;
    asm("{ .reg .u64 t; cvta.to.shared.u64 t, %1; cvt.u32.u64 %0, t; }" : "=r"(a) : "l"(p));
    return a;
}
__device__ __forceinline__ void cpa16(uint32_t dst, const void* src) {
    asm volatile("cp.async.cg.shared.global [%0], [%1], 16;" :: "r"(dst), "l"(src));
}
__device__ __forceinline__ void cpa4(uint32_t dst, const void* src) {
    asm volatile("cp.async.ca.shared.global [%0], [%1], 4;" :: "r"(dst), "l"(src));
}
#define CP_COMMIT() asm volatile("cp.async.commit_group;" ::: "memory")
#define CP_WAIT0()  asm volatile("cp.async.wait_group 0;" ::: "memory")
#define CP_WAIT1()  asm volatile("cp.async.wait_group 1;" ::: "memory")

__device__ __forceinline__ void ldsm4(uint32_t* r, uint32_t addr) {
    asm volatile("ldmatrix.sync.aligned.m8n8.x4.shared.b16 {%0,%1,%2,%3}, [%4];"
                 : "=r"(r[0]), "=r"(r[1]), "=r"(r[2]), "=r"(r[3]) : "r"(addr));
}
__device__ __forceinline__ void ldsm4t(uint32_t* r, uint32_t addr) {
    asm volatile("ldmatrix.sync.aligned.m8n8.x4.trans.shared.b16 {%0,%1,%2,%3}, [%4];"
                 : "=r"(r[0]), "=r"(r[1]), "=r"(r[2]), "=r"(r[3]) : "r"(addr));
}
__device__ __forceinline__ void mma_bf16(float* c, const uint32_t* a, const uint32_t* b) {
    asm volatile("mma.sync.aligned.m16n8k16.row.col.f32.bf16.bf16.f32 "
                 "{%0,%1,%2,%3}, {%4,%5,%6,%7}, {%8,%9}, {%0,%1,%2,%3};"
                 : "+f"(c[0]), "+f"(c[1]), "+f"(c[2]), "+f"(c[3])
                 : "r"(a[0]), "r"(a[1]), "r"(a[2]), "r"(a[3]), "r"(b[0]), "r"(b[1]));
}
__device__ __forceinline__ float ex2f(float x) {
    float r; asm("ex2.approx.f32 %0, %1;" : "=f"(r) : "f"(x)); return r;
}
// split pair (v0,v1) -> packed bf16 hi pair + bf16 lo-residual pair
__device__ __forceinline__ void split2(float v0, float v1, uint32_t& hi, uint32_t& lo) {
    uint32_t b0 = __float_as_uint(v0), b1 = __float_as_uint(v1);
    uint32_t h0 = (b0 + 0x7FFFu + ((b0 >> 16) & 1u)) & 0xFFFF0000u;
    uint32_t h1 = (b1 + 0x7FFFu + ((b1 >> 16) & 1u)) & 0xFFFF0000u;
    hi = (h0 >> 16) | h1;
    float l0 = v0 - __uint_as_float(h0);
    float l1 = v1 - __uint_as_float(h1);
    asm("cvt.rn.bf16x2.f32 %0, %1, %2;" : "=r"(lo) : "f"(l1), "f"(l0));
}

// ---------------- prep: fp32 -> bf16 hi/lo ----------------
__global__ void split_x_kernel(const float* __restrict__ src) {
    for (size_t i = (size_t)blockIdx.x * blockDim.x + threadIdx.x; i < (size_t)MTOK * D_MODEL;
         i += (size_t)gridDim.x * blockDim.x) {
        float v = src[i];
        __nv_bfloat16 h = __float2bfloat16(v);
        g_xh[i] = h;
        g_xl[i] = __float2bfloat16(v - __bfloat162float(h));
    }
}
__global__ void split_w_kernel(const float* __restrict__ w0, const float* __restrict__ w1,
                               const float* __restrict__ w2, const float* __restrict__ w3) {
    int idx = blockIdx.y;
    const float* src = (idx == 0) ? w0 : (idx == 1) ? w1 : (idx == 2) ? w2 : w3;
    size_t off = (size_t)idx * 1048576;
    for (size_t i = (size_t)blockIdx.x * blockDim.x + threadIdx.x; i < 1048576;
         i += (size_t)gridDim.x * blockDim.x) {
        float v = src[i];
        __nv_bfloat16 h = __float2bfloat16(v);
        g_wh[off + i] = h;
        g_wl[off + i] = __float2bfloat16(v - __bfloat162float(h));
    }
}

// ---------------- projection GEMM: C[8192,1024] = A @ W^T, split bf16, mma.sync ----
// OPROJ=0: QKV merged via blockIdx.z (0:Q scaled, 1:K, 2:V) -> hi/lo scratch
// OPROJ=1: O projection (g_c @ Wo^T + bias) -> fp32 out
// stage: 4 tiles x [128 rows x 32 k-elems], row stride 80B; 2-stage pipeline, 2 CTAs/SM
#define PST 40960

template<int OPROJ>
__global__ void __launch_bounds__(256, 2)
proj_kernel(const float* __restrict__ bias, float* __restrict__ out)
{
    extern __shared__ char smem[];
    const uint32_t sb = su32(smem);
    const int tid = threadIdx.x;
    const int lane = tid & 31, wid = tid >> 5;
    const int wm = wid >> 2, wn = wid & 3;
    const int g = lane >> 2, tig = lane & 3;
    const int m0 = blockIdx.x * 128, n0 = blockIdx.y * 128;
    const int mode = OPROJ ? 3 : (int)blockIdx.z;

    const __nv_bfloat16* Ah = OPROJ ? g_ch : g_xh;
    const __nv_bfloat16* Al = OPROJ ? g_cl : g_xl;
    const __nv_bfloat16* Bh = g_wh + (size_t)mode * 1048576;
    const __nv_bfloat16* Bl = g_wl + (size_t)mode * 1048576;

    float acc[4][4][4];
#pragma unroll
    for (int i = 0; i < 4; i++)
#pragma unroll
        for (int j = 0; j < 4; j++)
#pragma unroll
            for (int e = 0; e < 4; e++) acc[i][j][e] = 0.0f;

    auto load_stage = [&](int kt, int buf) {
        uint32_t base = sb + buf * PST;
#pragma unroll
        for (int t = 0; t < 8; t++) {
            int vi = tid + t * 256;
            int tile = vi >> 9;
            int row = (vi >> 2) & 127;
            int ch = vi & 3;
            const __nv_bfloat16* src;
            if      (tile == 0) src = Ah + (size_t)(m0 + row) * 1024 + kt + ch * 8;
            else if (tile == 1) src = Al + (size_t)(m0 + row) * 1024 + kt + ch * 8;
            else if (tile == 2) src = Bh + (size_t)(n0 + row) * 1024 + kt + ch * 8;
            else                src = Bl + (size_t)(n0 + row) * 1024 + kt + ch * 8;
            cpa16(base + tile * 10240 + row * 80 + ch * 16, src);
        }
        CP_COMMIT();
    };

    load_stage(0, 0);
    for (int s = 0; s < 32; s++) {
        if (s < 31) { load_stage((s + 1) * 32, (s + 1) & 1); CP_WAIT1(); }
        else CP_WAIT0();
        __syncthreads();
        uint32_t base = sb + (s & 1) * PST;
#pragma unroll
        for (int ks = 0; ks < 2; ks++) {
            uint32_t afh[4][4], afl[4][4];
#pragma unroll
            for (int mf = 0; mf < 4; mf++) {
                uint32_t a = base + (uint32_t)(wm * 64 + mf * 16 + (lane & 15)) * 80
                           + (ks * 16 + (lane >> 4) * 8) * 2;
                ldsm4(afh[mf], a);
                ldsm4(afl[mf], a + 10240);
            }
#pragma unroll
            for (int g2 = 0; g2 < 2; g2++) {
                uint32_t bfh[4], bfl[4];
                uint32_t a = base + 20480
                           + (uint32_t)(wn * 32 + g2 * 16 + (lane & 7) + ((lane >> 4) << 3)) * 80
                           + (ks * 16 + ((lane >> 3) & 1) * 8) * 2;
                ldsm4(bfh, a);
                ldsm4(bfl, a + 10240);
#pragma unroll
                for (int mf = 0; mf < 4; mf++)
#pragma unroll
                    for (int j = 0; j < 2; j++) {
                        float* c = acc[mf][g2 * 2 + j];
                        mma_bf16(c, afh[mf], &bfh[j * 2]);
                        mma_bf16(c, afh[mf], &bfl[j * 2]);
                        mma_bf16(c, afl[mf], &bfh[j * 2]);
                    }
            }
        }
        __syncthreads();
    }

    // epilogue
    const float scale = (mode == 0) ? QSCALE : 1.0f;
    __nv_bfloat16* Oh = (mode == 0) ? g_qh : (mode == 1) ? g_kh : g_vh;
    __nv_bfloat16* Ol = (mode == 0) ? g_ql : (mode == 1) ? g_kl : g_vl;
#pragma unroll
    for (int mf = 0; mf < 4; mf++) {
#pragma unroll
        for (int half = 0; half < 2; half++) {
            int m = m0 + wm * 64 + mf * 16 + g + half * 8;
#pragma unroll
            for (int nf = 0; nf < 4; nf++) {
                int n = n0 + wn * 32 + nf * 8 + 2 * tig;
                float v0 = acc[mf][nf][half * 2] * scale;
                float v1 = acc[mf][nf][half * 2 + 1] * scale;
                if (OPROJ) {
                    float2 o = make_float2(v0 + bias[n], v1 + bias[n + 1]);
                    *(float2*)(out + (size_t)m * 1024 + n) = o;
                } else {
                    int b = m >> 11, ss = m & 2047;
                    int h = n >> 6, d = n & 63;
                    size_t addr = (((size_t)(b * 16 + h) * 2048) + ss) * 64 + d;
                    uint32_t hi, lo;
                    split2(v0, v1, hi, lo);
                    *(uint32_t*)(Oh + addr) = hi;
                    *(uint32_t*)(Ol + addr) = lo;
                }
            }
        }
    }
}

// ---------------- attention: FA2 register-P, half-column passes, 2 CTAs/SM ----------------
// 8 warps x 16 q-rows. Q/K/V tiles: 128 x 64 bf16, stride 144B, tile 18432B.
// Single-buffered KV (occupancy covers load latency).
// SMEM: QH 0, QL 18432, KH 36864, KL 55296, VH 73728, VL 92160, SB 110592. Total 111616.
#define AT_TS  18432
#define AT_QH  0
#define AT_QL  18432
#define AT_KH  36864
#define AT_KL  55296
#define AT_VH  73728
#define AT_VL  92160
#define AT_SB  110592
#define AT_SMEM 111616

__global__ void __launch_bounds__(256, 2)
attn_kernel(const float* __restrict__ bias_table)
{
    extern __shared__ char smem[];
    const uint32_t sb = su32(smem);
    const int tid = threadIdx.x;
    const int lane = tid & 31, w = tid >> 5;
    const int g = lane >> 2, tig = lane & 3;
    const int bh = blockIdx.y;
    const int b = bh >> 4, h = bh & 15;
    const int q0 = blockIdx.x * 128;

    auto issue_kv = [&](int k0) {
#pragma unroll
        for (int u = 0; u < 16; u++) {
            int vi = tid + u * 256;
            int tile = vi >> 10;          // 0 KH,1 KL,2 VH,3 VL
            int row = (vi >> 3) & 127;
            int ch = vi & 7;
            const __nv_bfloat16* src;
            if      (tile == 0) src = g_kh + ((size_t)bh * 2048 + k0 + row) * 64 + ch * 8;
            else if (tile == 1) src = g_kl + ((size_t)bh * 2048 + k0 + row) * 64 + ch * 8;
            else if (tile == 2) src = g_vh + ((size_t)bh * 2048 + k0 + row) * 64 + ch * 8;
            else                src = g_vl + ((size_t)bh * 2048 + k0 + row) * 64 + ch * 8;
            cpa16(sb + AT_KH + tile * AT_TS + row * 144 + ch * 16, src);
        }
        if (tid < 255)
            cpa4(sb + AT_SB + tid * 4,
                 bias_table + (size_t)(q0 - k0 + 1920 + tid) * 16 + h);
    };

    // Q tiles hi/lo (once) + first KV, one group
#pragma unroll
    for (int t2 = 0; t2 < 8; t2++) {
        int vi = tid + t2 * 256;
        int half = vi >> 10;
        int row = (vi >> 3) & 127;
        int ch = vi & 7;
        const __nv_bfloat16* src = (half ? g_ql : g_qh)
            + ((size_t)bh * 2048 + q0 + row) * 64 + ch * 8;
        cpa16(sb + (half ? AT_QL : AT_QH) + row * 144 + ch * 16, src);
    }
    issue_kv(0);
    CP_COMMIT();

    float oacc[8][4];
#pragma unroll
    for (int i = 0; i < 8; i++)
#pragma unroll
        for (int e = 0; e < 4; e++) oacc[i][e] = 0.0f;
    float lsumA = 0.0f, lsumB = 0.0f;

    const int d0 = w * 16 + g - 2 * tig + 127;
    const float* sbias = (const float*)(smem + AT_SB);

    for (int t = 0; t < 16; t++) {
        if (t > 0) {
            __syncthreads();            // all warps done with previous KV
            issue_kv(t * 128);
            CP_COMMIT();
        }
        CP_WAIT0();
        __syncthreads();

#pragma unroll
        for (int half = 0; half < 2; half++) {
            // ---- S(half) = Q @ K[half]^T (log2-scaled), 64 cols ----
            float sacc[8][4];
#pragma unroll
            for (int i = 0; i < 8; i++)
#pragma unroll
                for (int e = 0; e < 4; e++) sacc[i][e] = 0.0f;
#pragma unroll
            for (int ks = 0; ks < 4; ks++) {
                uint32_t qfh[4], qfl[4];
                {
                    uint32_t a = sb + AT_QH + (uint32_t)(w * 16 + (lane & 15)) * 144
                               + (ks * 16 + (lane >> 4) * 8) * 2;
                    ldsm4(qfh, a);
                    ldsm4(qfl, a + AT_TS);
                }
                uint32_t kfh[4][4], kfl[4][4];
#pragma unroll
                for (int g2 = 0; g2 < 4; g2++) {
                    uint32_t a = sb + AT_KH
                        + (uint32_t)(half * 64 + g2 * 16 + (lane & 7) + ((lane >> 4) << 3)) * 144
                        + (ks * 16 + ((lane >> 3) & 1) * 8) * 2;
                    ldsm4(kfh[g2], a);
                    ldsm4(kfl[g2], a + AT_TS);
                }
#pragma unroll
                for (int nf2 = 0; nf2 < 8; nf2++) {
                    float* c = sacc[nf2];
                    const uint32_t* bhp = &kfh[nf2 >> 1][(nf2 & 1) * 2];
                    const uint32_t* blp = &kfl[nf2 >> 1][(nf2 & 1) * 2];
                    mma_bf16(c, qfh, bhp);
                    mma_bf16(c, qfh, blp);
                    mma_bf16(c, qfl, bhp);
                }
            }

            // ---- P(half) = 2^(S + bias*log2e): C-frag -> A-frag in registers ----
            uint32_t pfh[4][4], pfl[4][4];
#pragma unroll
            for (int ks2 = 0; ks2 < 4; ks2++) {
#pragma unroll
                for (int j = 0; j < 2; j++) {
                    int nf2 = 2 * ks2 + j;
                    float* c = sacc[nf2];
                    int idx = d0 - (half * 8 + nf2) * 8;
                    float p0 = ex2f(fmaf(sbias[idx],     LOG2E, c[0]));
                    float p1 = ex2f(fmaf(sbias[idx - 1], LOG2E, c[1]));
                    float p2 = ex2f(fmaf(sbias[idx + 8], LOG2E, c[2]));
                    float p3 = ex2f(fmaf(sbias[idx + 7], LOG2E, c[3]));
                    lsumA += p0 + p1;
                    lsumB += p2 + p3;
                    split2(p0, p1, pfh[ks2][j * 2 + 0], pfl[ks2][j * 2 + 0]);
                    split2(p2, p3, pfh[ks2][j * 2 + 1], pfl[ks2][j * 2 + 1]);
                }
            }

            // ---- O += P(half) @ V[half] ----
#pragma unroll
            for (int ks2 = 0; ks2 < 4; ks2++) {
                uint32_t vfh[4][4], vfl[4][4];
#pragma unroll
                for (int dblk = 0; dblk < 4; dblk++) {
                    uint32_t a = sb + AT_VH
                        + (uint32_t)(half * 64 + ks2 * 16 + (lane & 7) + ((lane >> 3) & 1) * 8) * 144
                        + (dblk * 16 + ((lane >> 4) << 3)) * 2;
                    ldsm4t(vfh[dblk], a);
                    ldsm4t(vfl[dblk], a + AT_TS);
                }
#pragma unroll
                for (int dblk = 0; dblk < 4; dblk++)
#pragma unroll
                    for (int sub = 0; sub < 2; sub++) {
                        float* o = oacc[dblk * 2 + sub];
                        mma_bf16(o, pfh[ks2], &vfh[dblk][sub * 2]);
                        mma_bf16(o, pfh[ks2], &vfl[dblk][sub * 2]);
                        mma_bf16(o, pfl[ks2], &vfh[dblk][sub * 2]);
                    }
            }
        }
    }

    // ---- row-sum reduce within quad, epilogue ----
    lsumA += __shfl_xor_sync(0xffffffffu, lsumA, 1);
    lsumA += __shfl_xor_sync(0xffffffffu, lsumA, 2);
    lsumB += __shfl_xor_sync(0xffffffffu, lsumB, 1);
    lsumB += __shfl_xor_sync(0xffffffffu, lsumB, 2);
    const float inv0 = 1.0f / lsumA;
    const float inv1 = 1.0f / lsumB;
    const int row0 = q0 + w * 16 + g;
    const size_t base0 = (size_t)(b * 2048 + row0) * 1024 + h * 64;
    const size_t base1 = (size_t)(b * 2048 + row0 + 8) * 1024 + h * 64;
#pragma unroll
    for (int nfd = 0; nfd < 8; nfd++) {
        int d = nfd * 8 + 2 * tig;
        uint32_t hi, lo;
        split2(oacc[nfd][0] * inv0, oacc[nfd][1] * inv0, hi, lo);
        *(uint32_t*)(g_ch + base0 + d) = hi;
        *(uint32_t*)(g_cl + base0 + d) = lo;
        split2(oacc[nfd][2] * inv1, oacc[nfd][3] * inv1, hi, lo);
        *(uint32_t*)(g_ch + base1 + d) = hi;
        *(uint32_t*)(g_cl + base1 + d) = lo;
    }
}

// ---------------- launch ----------------
extern "C" void kernel_launch(void* const* d_in, const int* in_sizes, int n_in,
                              void* d_out, int out_size)
{
    const float* x  = (const float*)d_in[0];
    const float* Wq = (const float*)d_in[1];
    const float* Wk = (const float*)d_in[2];
    const float* Wv = (const float*)d_in[3];
    const float* Wo = (const float*)d_in[4];
    const float* bo = (const float*)d_in[5];
    const float* bt = (const float*)d_in[6];
    float* out = (float*)d_out;

    cudaFuncSetAttribute(proj_kernel<0>, cudaFuncAttributeMaxDynamicSharedMemorySize, 2 * PST);
    cudaFuncSetAttribute(proj_kernel<1>, cudaFuncAttributeMaxDynamicSharedMemorySize, 2 * PST);
    cudaFuncSetAttribute(attn_kernel,    cudaFuncAttributeMaxDynamicSharedMemorySize, AT_SMEM);

    split_x_kernel<<<2048, 256>>>(x);
    split_w_kernel<<<dim3(256, 4), 256>>>(Wq, Wk, Wv, Wo);

    proj_kernel<0><<<dim3(64, 8, 3), 256, 2 * PST>>>(nullptr, nullptr);

    attn_kernel<<<dim3(16, 64), 256, AT_SMEM>>>(bt);

    proj_kernel<1><<<dim3(64, 8), 256, 2 * PST>>>(bo, out);
}